// round 4
// baseline (speedup 1.0000x reference)
#include <cuda_runtime.h>
#include <math.h>

#define NN   1024
#define EIN  4096
#define ET   5120
#define NTE  5119
#define C1   16
#define C2   7
#define INC  1433
#define SORT_M 8192
#define SMEM_BYTES 65536     // max(8192*8, 3*5120*4 + red)

// ---------------- device scratch ----------------
__device__ float  g_dig[NTE + 1];
__device__ float  g_h1[NN * C1];
__device__ float  g_h2[NN * C2];
__device__ float  g_tesum1[C1];
__device__ float  g_tesum2[C2];
__device__ float  g_agg1[NN * C1];
__device__ float  g_agg2[NN * C2];
__device__ float  g_cnt[NN];

__device__ __forceinline__ float f_inf() { return __int_as_float(0x7f800000); }

// ---------------- zero accumulators ----------------
__global__ void k_zero() {
    int t = blockIdx.x * blockDim.x + threadIdx.x;
    if (t < NN * C1) g_agg1[t] = 0.f;
    if (t < NN * C2) g_agg2[t] = 0.f;
    if (t < NN)      g_cnt[t]  = 0.f;
}

// ---------------- digamma table ----------------
__global__ void k_digamma() {
    int k = blockIdx.x * blockDim.x + threadIdx.x;
    if (k > NTE) return;
    if (k == 0) { g_dig[0] = 0.f; return; }
    double x = (double)k, r = 0.0;
    while (x < 8.0) { r -= 1.0 / x; x += 1.0; }
    double ix = 1.0 / x, ix2 = ix * ix;
    r += log(x) - 0.5 * ix
       - ix2 * ((1.0/12.0) - ix2 * ((1.0/120.0) - ix2 * (1.0/252.0)));
    g_dig[k] = (float)r;
}

// ---------------- layer-1 GEMM ----------------
__global__ void k_gemm1(const float* __restrict__ x,
                        const float* __restrict__ W1,
                        const float* __restrict__ b1) {
    int v    = blockIdx.x;
    int warp = threadIdx.x >> 5;
    int lane = threadIdx.x & 31;
    const float* xr = x  + (size_t)v    * INC;
    const float* wr = W1 + (size_t)warp * INC;
    float s = 0.f;
    for (int k = lane; k < INC; k += 32) s += xr[k] * wr[k];
    #pragma unroll
    for (int o = 16; o; o >>= 1) s += __shfl_xor_sync(0xffffffffu, s, o);
    if (lane == 0) g_h1[v * C1 + warp] = s + b1[warp];
}

// ---------------- fused: gather -> shared bitonic sort by y -> windowed KSG TE ----
__global__ __launch_bounds__(1024) void k_sortte(const int* __restrict__ ei, int layer) {
    extern __shared__ unsigned long long skey[];
    const int   c   = blockIdx.x;
    const float* h  = (layer == 1) ? g_h1 : g_h2;
    const int    C  = (layer == 1) ? C1 : C2;
    float*   tesum  = (layer == 1) ? g_tesum1 : g_tesum2;
    const int tid = threadIdx.x;

    // ---- phase 1: build order-preserving (y,idx) keys ----
    #pragma unroll
    for (int w = 0; w < 8; w++) {
        int t = tid + w * 1024;
        unsigned long long kv = 0xFFFFFFFFFFFFFFFFull;        // +INF padding
        if (t < NTE) {
            int s0 = (t < EIN) ? ei[t] : (t - EIN);
            unsigned u = __float_as_uint(h[s0 * C + c]);
            u = (u & 0x80000000u) ? ~u : (u | 0x80000000u);
            kv = ((unsigned long long)u << 32) | (unsigned)t;
        }
        skey[t] = kv;
    }
    __syncthreads();

    // ---- phase 2: bitonic sort in shared (ascending) ----
    for (int k = 2; k <= SORT_M; k <<= 1) {
        for (int j = k >> 1; j > 0; j >>= 1) {
            #pragma unroll
            for (int w = 0; w < 8; w++) {
                int i = tid + w * 1024;
                int l = i ^ j;
                if (l > i) {
                    unsigned long long a = skey[i], b = skey[l];
                    bool up = ((i & k) == 0);
                    if ((a > b) == up) { skey[i] = b; skey[l] = a; }
                }
            }
            __syncthreads();
        }
    }

    // ---- phase 3: decode keys to regs, gather x/z, repack shared as SoA ----
    float xw[8], yw[8], zw[8];
    #pragma unroll
    for (int w = 0; w < 8; w++) {
        int t = tid + w * 1024;
        unsigned long long kv = skey[t];
        unsigned u  = (unsigned)(kv >> 32);
        unsigned yb = (u & 0x80000000u) ? (u & 0x7FFFFFFFu) : ~u;
        yw[w] = __uint_as_float(yb);
        xw[w] = 0.f; zw[w] = 0.f;
        if (t < NTE) {
            int i  = (int)(unsigned)(kv & 0xFFFFFFFFu);
            int d0 = (i < EIN) ? ei[EIN + i] : (i - EIN);
            int i1 = i + 1;
            int s1 = (i1 < EIN) ? ei[i1] : (i1 - EIN);
            xw[w] = h[d0 * C + c];
            zw[w] = h[s1 * C + c];
        }
    }
    __syncthreads();
    float* SX = (float*)skey;
    float* SY = SX + 5120;
    float* SZ = SY + 5120;
    float* red = SZ + 5120;       // 32 floats, still < 64KB
    #pragma unroll
    for (int w = 0; w < 8; w++) {
        int t = tid + w * 1024;
        if (t < NTE) { SX[t] = xw[w]; SY[t] = yw[w]; SZ[t] = zw[w]; }
    }
    __syncthreads();

    // ---- phase 4: KSG TE via sorted-y window walks (all in shared) ----
    float val = 0.f;
    for (int p = tid; p < NTE; p += 1024) {
        float xi = SX[p], yi = SY[p], zi = SZ[p];

        // eps: expanding two-pointer nearest-neighbor (Chebyshev) search
        float eps = f_inf();
        int lo = p - 1, hi = p + 1;
        float dyl = (lo >= 0)  ? (yi - SY[lo]) : f_inf();
        float dyr = (hi < NTE) ? (SY[hi] - yi) : f_inf();
        while (true) {
            if (dyl <= dyr) {
                if (dyl >= eps) break;
                float m = fmaxf(dyl, fmaxf(fabsf(xi - SX[lo]), fabsf(zi - SZ[lo])));
                eps = fminf(eps, m);
                lo--;
                dyl = (lo >= 0) ? (yi - SY[lo]) : f_inf();
            } else {
                if (dyr >= eps) break;
                float m = fmaxf(dyr, fmaxf(fabsf(xi - SX[hi]), fabsf(zi - SZ[hi])));
                eps = fminf(eps, m);
                hi++;
                dyr = (hi < NTE) ? (SY[hi] - yi) : f_inf();
            }
        }

        // counts over the dy<eps window (self contributes 1 to each)
        int cy = 1, cxy = 1, cyz = 1;
        for (int j = p - 1; j >= 0; j--) {
            float dy = yi - SY[j];
            if (!(dy < eps)) break;
            cy++;
            cxy += (fabsf(xi - SX[j]) < eps);
            cyz += (fabsf(zi - SZ[j]) < eps);
        }
        for (int j = p + 1; j < NTE; j++) {
            float dy = SY[j] - yi;
            if (!(dy < eps)) break;
            cy++;
            cxy += (fabsf(xi - SX[j]) < eps);
            cyz += (fabsf(zi - SZ[j]) < eps);
        }
        val += g_dig[cy] - g_dig[cxy] - g_dig[cyz];
    }

    #pragma unroll
    for (int o = 16; o; o >>= 1) val += __shfl_xor_sync(0xffffffffu, val, o);
    int lane = tid & 31, w = tid >> 5;
    if (lane == 0) red[w] = val;
    __syncthreads();
    if (tid == 0) {
        float s = 0.f;
        #pragma unroll
        for (int q = 0; q < 32; q++) s += red[q];
        tesum[c] = s;
    }
}

// ---------------- aggregation ----------------
__global__ void k_agg(const int* __restrict__ ei, int layer, int C) {
    int idx = blockIdx.x * blockDim.x + threadIdx.x;
    if (idx >= ET * C) return;
    const float* h     = (layer == 1) ? g_h1 : g_h2;
    const float* tesum = (layer == 1) ? g_tesum1 : g_tesum2;
    float*       agg   = (layer == 1) ? g_agg1 : g_agg2;
    int e = idx / C, c = idx - e * C;
    int s = (e < EIN) ? ei[e]       : (e - EIN);
    int d = (e < EIN) ? ei[EIN + e] : (e - EIN);
    float tes = -0.57721566490153286f + tesum[c] * (1.0f / (float)NTE);
    if (layer == 2) tes *= 0.5f;
    float m = 1.0f / (1.0f + expf(-tes * h[s * C + c]));
    atomicAdd(&agg[d * C + c], m);
    if (layer == 1 && c == 0) atomicAdd(&g_cnt[d], 1.0f);
}

// ---------------- layer-2 GEMM ----------------
__global__ void k_gemm2(const float* __restrict__ W2, const float* __restrict__ b2) {
    int v = blockIdx.x * blockDim.x + threadIdx.x;
    if (v >= NN) return;
    float inv = 1.0f / fmaxf(g_cnt[v], 1.0f);
    float hv[C1];
    #pragma unroll
    for (int cc = 0; cc < C1; cc++) hv[cc] = fmaxf(g_agg1[v * C1 + cc] * inv, 0.0f);
    #pragma unroll
    for (int o = 0; o < C2; o++) {
        float s = b2[o];
        #pragma unroll
        for (int cc = 0; cc < C1; cc++) s += W2[o * C1 + cc] * hv[cc];
        g_h2[v * C2 + o] = s;
    }
}

// ---------------- final: mean + log_softmax ----------------
__global__ void k_final(float* __restrict__ out) {
    int v = blockIdx.x * blockDim.x + threadIdx.x;
    if (v >= NN) return;
    float inv = 1.0f / fmaxf(g_cnt[v], 1.0f);
    float val[C2], mx = -f_inf();
    #pragma unroll
    for (int o = 0; o < C2; o++) {
        val[o] = g_agg2[v * C2 + o] * inv;
        mx = fmaxf(mx, val[o]);
    }
    float s = 0.f;
    #pragma unroll
    for (int o = 0; o < C2; o++) s += expf(val[o] - mx);
    float ls = mx + logf(s);
    #pragma unroll
    for (int o = 0; o < C2; o++) out[v * C2 + o] = val[o] - ls;
}

// ---------------- launch (inputs identified by element count) ----------------
extern "C" void kernel_launch(void* const* d_in, const int* in_sizes, int n_in,
                              void* d_out, int out_size) {
    const float* x  = nullptr;
    const int*   ei = nullptr;
    const float* W1 = nullptr;
    const float* b1 = nullptr;
    const float* W2 = nullptr;
    const float* b2 = nullptr;
    for (int k = 0; k < n_in; k++) {
        switch (in_sizes[k]) {
            case NN * INC:  x  = (const float*)d_in[k]; break;
            case 2 * EIN:   ei = (const int*)  d_in[k]; break;
            case C1 * INC:  W1 = (const float*)d_in[k]; break;
            case C1:        b1 = (const float*)d_in[k]; break;
            case C2 * C1:   W2 = (const float*)d_in[k]; break;
            case C2:        b2 = (const float*)d_in[k]; break;
            default: break;
        }
    }
    float* out = (float*)d_out;

    static bool attr_done = false;
    if (!attr_done) {
        cudaFuncSetAttribute(k_sortte, cudaFuncAttributeMaxDynamicSharedMemorySize, SMEM_BYTES);
        attr_done = true;
    }

    k_zero   <<<(NN * C1 + 255) / 256, 256>>>();
    k_digamma<<<(NTE + 1 + 255) / 256, 256>>>();

    // layer 1
    k_gemm1  <<<NN, 512>>>(x, W1, b1);
    k_sortte <<<C1, 1024, SMEM_BYTES>>>(ei, 1);
    k_agg    <<<(ET * C1 + 255) / 256, 256>>>(ei, 1, C1);

    // layer 2
    k_gemm2  <<<(NN + 255) / 256, 256>>>(W2, b2);
    k_sortte <<<C2, 1024, SMEM_BYTES>>>(ei, 2);
    k_agg    <<<(ET * C2 + 255) / 256, 256>>>(ei, 2, C2);

    k_final  <<<(NN + 255) / 256, 256>>>(out);
}

// round 5
// speedup vs baseline: 15.5427x; 15.5427x over previous
#include <cuda_runtime.h>
#include <math.h>

#define NN   1024
#define EIN  4096
#define ET   5120
#define NTE  5119
#define C1   16
#define C2   7
#define INC  1433
#define WPB  8                        // warps per TE block
#define BPC  ((NTE + WPB - 1) / WPB)  // 640 blocks per channel

// ---------------- device scratch ----------------
__device__ float  g_dig[NTE + 1];
__device__ float  g_h1[NN * C1];
__device__ float  g_h2[NN * C2];
__device__ float  g_sx[C1 * NTE], g_sy[C1 * NTE], g_sz[C1 * NTE];
__device__ float  g_tesum1[C1];
__device__ float  g_tesum2[C2];
__device__ float  g_agg1[NN * C1];
__device__ float  g_agg2[NN * C2];
__device__ float  g_cnt[NN];

__device__ __forceinline__ float f_inf() { return __int_as_float(0x7f800000); }

// ---------------- zero accumulators ----------------
__global__ void k_zero() {
    int t = blockIdx.x * blockDim.x + threadIdx.x;
    if (t < NN * C1) g_agg1[t] = 0.f;
    if (t < NN * C2) g_agg2[t] = 0.f;
    if (t < NN)      g_cnt[t]  = 0.f;
    if (t < C1)      g_tesum1[t] = 0.f;
    if (t < C2)      g_tesum2[t] = 0.f;
}

// ---------------- digamma table ----------------
__global__ void k_digamma() {
    int k = blockIdx.x * blockDim.x + threadIdx.x;
    if (k > NTE) return;
    if (k == 0) { g_dig[0] = 0.f; return; }
    double x = (double)k, r = 0.0;
    while (x < 8.0) { r -= 1.0 / x; x += 1.0; }
    double ix = 1.0 / x, ix2 = ix * ix;
    r += log(x) - 0.5 * ix
       - ix2 * ((1.0/12.0) - ix2 * ((1.0/120.0) - ix2 * (1.0/252.0)));
    g_dig[k] = (float)r;
}

// ---------------- layer-1 GEMM ----------------
__global__ void k_gemm1(const float* __restrict__ x,
                        const float* __restrict__ W1,
                        const float* __restrict__ b1) {
    int v    = blockIdx.x;
    int warp = threadIdx.x >> 5;
    int lane = threadIdx.x & 31;
    const float* xr = x  + (size_t)v    * INC;
    const float* wr = W1 + (size_t)warp * INC;
    float s = 0.f;
    for (int k = lane; k < INC; k += 32) s += xr[k] * wr[k];
    #pragma unroll
    for (int o = 16; o; o >>= 1) s += __shfl_xor_sync(0xffffffffu, s, o);
    if (lane == 0) g_h1[v * C1 + warp] = s + b1[warp];
}

// ------- sort samples by y: sort 1024 node values, then histogram+scan+scatter -------
__global__ __launch_bounds__(1024) void k_sort(const int* __restrict__ ei, int layer) {
    __shared__ unsigned long long key[1024];
    __shared__ int rankof[1024];
    __shared__ int cnt[1024];
    __shared__ int offs[1024];
    const int c   = blockIdx.x;
    const int tid = threadIdx.x;
    const float* h = (layer == 1) ? g_h1 : g_h2;
    const int    C = (layer == 1) ? C1 : C2;

    // encode node value -> order-preserving u32, append node id
    {
        unsigned u = __float_as_uint(h[tid * C + c]);
        u = (u & 0x80000000u) ? ~u : (u | 0x80000000u);
        key[tid] = ((unsigned long long)u << 32) | (unsigned)tid;
        cnt[tid] = 0;
    }
    __syncthreads();

    // bitonic sort of 1024 keys
    for (int k = 2; k <= 1024; k <<= 1) {
        for (int j = k >> 1; j > 0; j >>= 1) {
            int l = tid ^ j;
            if (l > tid) {
                unsigned long long a = key[tid], b = key[l];
                bool up = ((tid & k) == 0);
                if ((a > b) == up) { key[tid] = b; key[l] = a; }
            }
            __syncthreads();
        }
    }

    rankof[(int)(key[tid] & 1023u)] = tid;
    __syncthreads();

    // histogram of samples by rank of src node
    for (int t = tid; t < NTE; t += 1024) {
        int s0 = (t < EIN) ? ei[t] : (t - EIN);
        atomicAdd(&cnt[rankof[s0]], 1);
    }
    __syncthreads();

    // exclusive prefix scan (Hillis-Steele)
    int orig = cnt[tid];
    for (int off = 1; off < 1024; off <<= 1) {
        int add = (tid >= off) ? cnt[tid - off] : 0;
        __syncthreads();
        cnt[tid] += add;
        __syncthreads();
    }
    offs[tid] = cnt[tid] - orig;
    __syncthreads();

    // scatter samples into y-sorted slots (tie order irrelevant)
    float* SX = g_sx + (size_t)c * NTE;
    float* SY = g_sy + (size_t)c * NTE;
    float* SZ = g_sz + (size_t)c * NTE;
    for (int t = tid; t < NTE; t += 1024) {
        int s0 = (t < EIN) ? ei[t]       : (t - EIN);
        int d0 = (t < EIN) ? ei[EIN + t] : (t - EIN);
        int t1 = t + 1;
        int s1 = (t1 < EIN) ? ei[t1]     : (t1 - EIN);
        int slot = atomicAdd(&offs[rankof[s0]], 1);
        SX[slot] = h[d0 * C + c];
        SY[slot] = h[s0 * C + c];
        SZ[slot] = h[s1 * C + c];
    }
}

// ---------------- KSG TE: one warp per point, warp-parallel window scans ----------------
__global__ __launch_bounds__(32 * WPB) void k_te(int layer) {
    float* tesum = (layer == 1) ? g_tesum1 : g_tesum2;
    const int c  = blockIdx.x / BPC;
    const int bi = blockIdx.x - c * BPC;
    const int wid  = threadIdx.x >> 5;
    const int lane = threadIdx.x & 31;
    const int p    = bi * WPB + wid;
    const unsigned FULL = 0xffffffffu;

    const float* __restrict__ X = g_sx + (size_t)c * NTE;
    const float* __restrict__ Y = g_sy + (size_t)c * NTE;
    const float* __restrict__ Z = g_sz + (size_t)c * NTE;

    float val = 0.f;
    if (p < NTE) {
        float xi = X[p], yi = Y[p], zi = Z[p];

        // ---- phase A: eps (exact, chunked, pruned via monotone dy) ----
        float eps = f_inf();
        for (int jb = p - 1; jb >= 0; jb -= 32) {            // left
            int j = jb - lane;
            bool v = (j >= 0);
            int jc = v ? j : 0;
            float dy = v ? (yi - Y[jc]) : f_inf();
            float m  = v ? fmaxf(dy, fmaxf(fabsf(xi - X[jc]), fabsf(zi - Z[jc]))) : f_inf();
            unsigned mu = __reduce_min_sync(FULL, __float_as_uint(m));   // m >= 0
            eps = fminf(eps, __uint_as_float(mu));
            float dyf = __shfl_sync(FULL, dy, 31);           // farthest in chunk
            if (!(dyf < eps)) break;
        }
        for (int jb = p + 1; jb < NTE; jb += 32) {           // right
            int j = jb + lane;
            bool v = (j < NTE);
            int jc = v ? j : (NTE - 1);
            float dy = v ? (Y[jc] - yi) : f_inf();
            float m  = v ? fmaxf(dy, fmaxf(fabsf(xi - X[jc]), fabsf(zi - Z[jc]))) : f_inf();
            unsigned mu = __reduce_min_sync(FULL, __float_as_uint(m));
            eps = fminf(eps, __uint_as_float(mu));
            float dyf = __shfl_sync(FULL, dy, 31);
            if (!(dyf < eps)) break;
        }

        // ---- phase B: counts over dy<eps window (self contributes 1 each) ----
        int cy = 1, cxy = 1, cyz = 1;
        for (int jb = p - 1; jb >= 0; jb -= 32) {            // left
            int j = jb - lane;
            bool v = (j >= 0);
            int jc = v ? j : 0;
            float dy = v ? (yi - Y[jc]) : f_inf();
            bool in = (dy < eps);
            unsigned by = __ballot_sync(FULL, in);
            if (!by) break;
            cy  += __popc(by);
            cxy += __popc(__ballot_sync(FULL, in && (fabsf(xi - X[jc]) < eps)));
            cyz += __popc(__ballot_sync(FULL, in && (fabsf(zi - Z[jc]) < eps)));
            if (by != FULL) break;                           // dy monotone -> prefix ended
        }
        for (int jb = p + 1; jb < NTE; jb += 32) {           // right
            int j = jb + lane;
            bool v = (j < NTE);
            int jc = v ? j : (NTE - 1);
            float dy = v ? (Y[jc] - yi) : f_inf();
            bool in = v && (dy < eps);
            unsigned by = __ballot_sync(FULL, in);
            if (!by) break;
            cy  += __popc(by);
            cxy += __popc(__ballot_sync(FULL, in && (fabsf(xi - X[jc]) < eps)));
            cyz += __popc(__ballot_sync(FULL, in && (fabsf(zi - Z[jc]) < eps)));
            if (by != FULL) break;
        }
        val = g_dig[cy] - g_dig[cxy] - g_dig[cyz];           // warp-uniform
    }

    __shared__ float red[WPB];
    if (lane == 0) red[wid] = val;
    __syncthreads();
    if (threadIdx.x == 0) {
        float s = 0.f;
        #pragma unroll
        for (int q = 0; q < WPB; q++) s += red[q];
        atomicAdd(&tesum[c], s);
    }
}

// ---------------- aggregation ----------------
__global__ void k_agg(const int* __restrict__ ei, int layer, int C) {
    int idx = blockIdx.x * blockDim.x + threadIdx.x;
    if (idx >= ET * C) return;
    const float* h     = (layer == 1) ? g_h1 : g_h2;
    const float* tesum = (layer == 1) ? g_tesum1 : g_tesum2;
    float*       agg   = (layer == 1) ? g_agg1 : g_agg2;
    int e = idx / C, c = idx - e * C;
    int s = (e < EIN) ? ei[e]       : (e - EIN);
    int d = (e < EIN) ? ei[EIN + e] : (e - EIN);
    float tes = -0.57721566490153286f + tesum[c] * (1.0f / (float)NTE);
    if (layer == 2) tes *= 0.5f;
    float m = 1.0f / (1.0f + expf(-tes * h[s * C + c]));
    atomicAdd(&agg[d * C + c], m);
    if (layer == 1 && c == 0) atomicAdd(&g_cnt[d], 1.0f);
}

// ---------------- layer-2 GEMM ----------------
__global__ void k_gemm2(const float* __restrict__ W2, const float* __restrict__ b2) {
    int v = blockIdx.x * blockDim.x + threadIdx.x;
    if (v >= NN) return;
    float inv = 1.0f / fmaxf(g_cnt[v], 1.0f);
    float hv[C1];
    #pragma unroll
    for (int cc = 0; cc < C1; cc++) hv[cc] = fmaxf(g_agg1[v * C1 + cc] * inv, 0.0f);
    #pragma unroll
    for (int o = 0; o < C2; o++) {
        float s = b2[o];
        #pragma unroll
        for (int cc = 0; cc < C1; cc++) s += W2[o * C1 + cc] * hv[cc];
        g_h2[v * C2 + o] = s;
    }
}

// ---------------- final: mean + log_softmax ----------------
__global__ void k_final(float* __restrict__ out) {
    int v = blockIdx.x * blockDim.x + threadIdx.x;
    if (v >= NN) return;
    float inv = 1.0f / fmaxf(g_cnt[v], 1.0f);
    float val[C2], mx = -f_inf();
    #pragma unroll
    for (int o = 0; o < C2; o++) {
        val[o] = g_agg2[v * C2 + o] * inv;
        mx = fmaxf(mx, val[o]);
    }
    float s = 0.f;
    #pragma unroll
    for (int o = 0; o < C2; o++) s += expf(val[o] - mx);
    float ls = mx + logf(s);
    #pragma unroll
    for (int o = 0; o < C2; o++) out[v * C2 + o] = val[o] - ls;
}

// ---------------- launch (inputs identified by element count) ----------------
extern "C" void kernel_launch(void* const* d_in, const int* in_sizes, int n_in,
                              void* d_out, int out_size) {
    const float* x  = nullptr;
    const int*   ei = nullptr;
    const float* W1 = nullptr;
    const float* b1 = nullptr;
    const float* W2 = nullptr;
    const float* b2 = nullptr;
    for (int k = 0; k < n_in; k++) {
        switch (in_sizes[k]) {
            case NN * INC:  x  = (const float*)d_in[k]; break;
            case 2 * EIN:   ei = (const int*)  d_in[k]; break;
            case C1 * INC:  W1 = (const float*)d_in[k]; break;
            case C1:        b1 = (const float*)d_in[k]; break;
            case C2 * C1:   W2 = (const float*)d_in[k]; break;
            case C2:        b2 = (const float*)d_in[k]; break;
            default: break;
        }
    }
    float* out = (float*)d_out;

    k_zero   <<<(NN * C1 + 255) / 256, 256>>>();
    k_digamma<<<(NTE + 1 + 255) / 256, 256>>>();

    // layer 1
    k_gemm1  <<<NN, 512>>>(x, W1, b1);
    k_sort   <<<C1, 1024>>>(ei, 1);
    k_te     <<<C1 * BPC, 32 * WPB>>>(1);
    k_agg    <<<(ET * C1 + 255) / 256, 256>>>(ei, 1, C1);

    // layer 2
    k_gemm2  <<<(NN + 255) / 256, 256>>>(W2, b2);
    k_sort   <<<C2, 1024>>>(ei, 2);
    k_te     <<<C2 * BPC, 32 * WPB>>>(2);
    k_agg    <<<(ET * C2 + 255) / 256, 256>>>(ei, 2, C2);

    k_final  <<<(NN + 255) / 256, 256>>>(out);
}

// round 6
// speedup vs baseline: 17.9416x; 1.1543x over previous
#include <cuda_runtime.h>
#include <math.h>

#define NN   1024
#define EIN  4096
#define ET   5120
#define NTE  5119
#define C1   16
#define C2   7
#define INC  1433
#define WPB  8                        // warps per TE block
#define BPC  ((NTE + WPB - 1) / WPB)  // 640 blocks per channel

// ---------------- device scratch ----------------
__device__ float  g_dig[NTE + 1];
__device__ float  g_h1[NN * C1];
__device__ float  g_h2[NN * C2];
__device__ float4 g_s4[C1 * NTE];
__device__ float  g_tesum1[C1];
__device__ float  g_tesum2[C2];
__device__ float  g_agg1[NN * C1];
__device__ float  g_agg2[NN * C2];
__device__ float  g_cnt[NN];

__device__ __forceinline__ float f_inf() { return __int_as_float(0x7f800000); }

// ---------------- init: zero accumulators + digamma table ----------------
__global__ void k_init() {
    int t = blockIdx.x * blockDim.x + threadIdx.x;
    if (t < NN * C1) g_agg1[t] = 0.f;
    if (t < NN * C2) g_agg2[t] = 0.f;
    if (t < NN)      g_cnt[t]  = 0.f;
    if (t < C1)      g_tesum1[t] = 0.f;
    if (t < C2)      g_tesum2[t] = 0.f;
    if (t <= NTE) {
        if (t == 0) { g_dig[0] = 0.f; return; }
        double x = (double)t, r = 0.0;
        while (x < 8.0) { r -= 1.0 / x; x += 1.0; }
        double ix = 1.0 / x, ix2 = ix * ix;
        r += log(x) - 0.5 * ix
           - ix2 * ((1.0/12.0) - ix2 * ((1.0/120.0) - ix2 * (1.0/252.0)));
        g_dig[t] = (float)r;
    }
}

// ---------------- layer-1 GEMM ----------------
__global__ void k_gemm1(const float* __restrict__ x,
                        const float* __restrict__ W1,
                        const float* __restrict__ b1) {
    int v    = blockIdx.x;
    int warp = threadIdx.x >> 5;
    int lane = threadIdx.x & 31;
    const float* xr = x  + (size_t)v    * INC;
    const float* wr = W1 + (size_t)warp * INC;
    float s = 0.f;
    for (int k = lane; k < INC; k += 32) s += xr[k] * wr[k];
    #pragma unroll
    for (int o = 16; o; o >>= 1) s += __shfl_xor_sync(0xffffffffu, s, o);
    if (lane == 0) g_h1[v * C1 + warp] = s + b1[warp];
}

// ------- sort samples by y: hybrid warp/shared bitonic over 1024 node values,
//         then histogram + scan + scatter of the 5119 samples -------
__global__ __launch_bounds__(1024) void k_sort(const int* __restrict__ ei, int layer) {
    __shared__ unsigned long long sk[1024];
    __shared__ int rankof[1024];
    __shared__ int cnt[1024];
    __shared__ int offs[1024];
    const int c   = blockIdx.x;
    const int tid = threadIdx.x;
    const int lane = tid & 31;
    const float* h = (layer == 1) ? g_h1 : g_h2;
    const int    C = (layer == 1) ? C1 : C2;
    const unsigned FULL = 0xffffffffu;

    // order-preserving (value,node) key in a register
    unsigned long long kv;
    {
        unsigned u = __float_as_uint(h[tid * C + c]);
        u = (u & 0x80000000u) ? ~u : (u | 0x80000000u);
        kv = ((unsigned long long)u << 32) | (unsigned)tid;
        cnt[tid] = 0;
    }

    // bitonic: j<32 via shuffles (register), j>=32 via shared
    for (int k = 2; k <= 1024; k <<= 1) {
        for (int j = k >> 1; j > 0; j >>= 1) {
            bool up = ((tid & k) == 0);
            unsigned long long other;
            if (j >= 32) {
                __syncthreads();
                sk[tid] = kv;
                __syncthreads();
                other = sk[tid ^ j];
            } else {
                other = __shfl_xor_sync(FULL, kv, j);
            }
            bool keepmin = (((tid & j) == 0) == up);
            bool swap = keepmin ? (other < kv) : (other > kv);
            if (swap) kv = other;
        }
    }
    __syncthreads();
    rankof[(int)(kv & 1023u)] = tid;
    __syncthreads();

    // histogram of samples by rank of src node
    for (int t = tid; t < NTE; t += 1024) {
        int s0 = (t < EIN) ? ei[t] : (t - EIN);
        atomicAdd(&cnt[rankof[s0]], 1);
    }
    __syncthreads();

    // exclusive prefix scan (Hillis-Steele)
    int orig = cnt[tid];
    for (int off = 1; off < 1024; off <<= 1) {
        int add = (tid >= off) ? cnt[tid - off] : 0;
        __syncthreads();
        cnt[tid] += add;
        __syncthreads();
    }
    offs[tid] = cnt[tid] - orig;
    __syncthreads();

    // scatter samples into y-sorted slots (tie order irrelevant: predicates value-based)
    float4* S = g_s4 + (size_t)c * NTE;
    for (int t = tid; t < NTE; t += 1024) {
        int s0 = (t < EIN) ? ei[t]       : (t - EIN);
        int d0 = (t < EIN) ? ei[EIN + t] : (t - EIN);
        int t1 = t + 1;
        int s1 = (t1 < EIN) ? ei[t1]     : (t1 - EIN);
        int slot = atomicAdd(&offs[rankof[s0]], 1);
        S[slot] = make_float4(h[d0 * C + c], h[s0 * C + c], h[s1 * C + c], 0.f);
    }
}

// ---------------- KSG TE: one warp per point, warp-parallel window scans ----------------
__global__ __launch_bounds__(32 * WPB) void k_te(int layer) {
    float* tesum = (layer == 1) ? g_tesum1 : g_tesum2;
    const int c  = blockIdx.x / BPC;
    const int bi = blockIdx.x - c * BPC;
    const int wid  = threadIdx.x >> 5;
    const int lane = threadIdx.x & 31;
    const int p    = bi * WPB + wid;
    const unsigned FULL = 0xffffffffu;

    const float4* __restrict__ S = g_s4 + (size_t)c * NTE;

    float val = 0.f;
    if (p < NTE) {
        float4 pi = S[p];
        float xi = pi.x, yi = pi.y, zi = pi.z;

        // ---- phase A: eps (exact, chunked, pruned via monotone dy) ----
        float eps = f_inf();
        for (int jb = p - 1; jb >= 0; jb -= 32) {            // left
            int j = jb - lane;
            bool v = (j >= 0);
            float4 q = S[v ? j : 0];
            float dy = v ? (yi - q.y) : f_inf();
            float m  = v ? fmaxf(dy, fmaxf(fabsf(xi - q.x), fabsf(zi - q.z))) : f_inf();
            unsigned mu = __reduce_min_sync(FULL, __float_as_uint(m));   // m >= 0
            eps = fminf(eps, __uint_as_float(mu));
            float dyf = __shfl_sync(FULL, dy, 31);           // farthest in chunk
            if (!(dyf < eps)) break;
        }
        for (int jb = p + 1; jb < NTE; jb += 32) {           // right
            int j = jb + lane;
            bool v = (j < NTE);
            float4 q = S[v ? j : (NTE - 1)];
            float dy = v ? (q.y - yi) : f_inf();
            float m  = v ? fmaxf(dy, fmaxf(fabsf(xi - q.x), fabsf(zi - q.z))) : f_inf();
            unsigned mu = __reduce_min_sync(FULL, __float_as_uint(m));
            eps = fminf(eps, __uint_as_float(mu));
            float dyf = __shfl_sync(FULL, dy, 31);
            if (!(dyf < eps)) break;
        }

        // ---- phase B: counts over dy<eps window (self contributes 1 each) ----
        int cy = 1, cxy = 1, cyz = 1;
        for (int jb = p - 1; jb >= 0; jb -= 32) {            // left
            int j = jb - lane;
            bool v = (j >= 0);
            float4 q = S[v ? j : 0];
            float dy = v ? (yi - q.y) : f_inf();
            bool in = (dy < eps);
            unsigned by = __ballot_sync(FULL, in);
            if (!by) break;
            cy  += __popc(by);
            cxy += __popc(__ballot_sync(FULL, in && (fabsf(xi - q.x) < eps)));
            cyz += __popc(__ballot_sync(FULL, in && (fabsf(zi - q.z) < eps)));
            if (by != FULL) break;                           // dy monotone -> prefix ended
        }
        for (int jb = p + 1; jb < NTE; jb += 32) {           // right
            int j = jb + lane;
            bool v = (j < NTE);
            float4 q = S[v ? j : (NTE - 1)];
            float dy = v ? (q.y - yi) : f_inf();
            bool in = v && (dy < eps);
            unsigned by = __ballot_sync(FULL, in);
            if (!by) break;
            cy  += __popc(by);
            cxy += __popc(__ballot_sync(FULL, in && (fabsf(xi - q.x) < eps)));
            cyz += __popc(__ballot_sync(FULL, in && (fabsf(zi - q.z) < eps)));
            if (by != FULL) break;
        }
        val = g_dig[cy] - g_dig[cxy] - g_dig[cyz];           // warp-uniform
    }

    __shared__ float red[WPB];
    if (lane == 0) red[wid] = val;
    __syncthreads();
    if (threadIdx.x == 0) {
        float s = 0.f;
        #pragma unroll
        for (int q = 0; q < WPB; q++) s += red[q];
        atomicAdd(&tesum[c], s);
    }
}

// ---------------- aggregation ----------------
__global__ void k_agg(const int* __restrict__ ei, int layer, int C) {
    int idx = blockIdx.x * blockDim.x + threadIdx.x;
    if (idx >= ET * C) return;
    const float* h     = (layer == 1) ? g_h1 : g_h2;
    const float* tesum = (layer == 1) ? g_tesum1 : g_tesum2;
    float*       agg   = (layer == 1) ? g_agg1 : g_agg2;
    int e = idx / C, c = idx - e * C;
    int s = (e < EIN) ? ei[e]       : (e - EIN);
    int d = (e < EIN) ? ei[EIN + e] : (e - EIN);
    float tes = -0.57721566490153286f + tesum[c] * (1.0f / (float)NTE);
    if (layer == 2) tes *= 0.5f;
    float m = 1.0f / (1.0f + expf(-tes * h[s * C + c]));
    atomicAdd(&agg[d * C + c], m);
    if (layer == 1 && c == 0) atomicAdd(&g_cnt[d], 1.0f);
}

// ---------------- layer-2 GEMM ----------------
__global__ void k_gemm2(const float* __restrict__ W2, const float* __restrict__ b2) {
    int v = blockIdx.x * blockDim.x + threadIdx.x;
    if (v >= NN) return;
    float inv = 1.0f / fmaxf(g_cnt[v], 1.0f);
    float hv[C1];
    #pragma unroll
    for (int cc = 0; cc < C1; cc++) hv[cc] = fmaxf(g_agg1[v * C1 + cc] * inv, 0.0f);
    #pragma unroll
    for (int o = 0; o < C2; o++) {
        float s = b2[o];
        #pragma unroll
        for (int cc = 0; cc < C1; cc++) s += W2[o * C1 + cc] * hv[cc];
        g_h2[v * C2 + o] = s;
    }
}

// ---------------- final: mean + log_softmax ----------------
__global__ void k_final(float* __restrict__ out) {
    int v = blockIdx.x * blockDim.x + threadIdx.x;
    if (v >= NN) return;
    float inv = 1.0f / fmaxf(g_cnt[v], 1.0f);
    float val[C2], mx = -f_inf();
    #pragma unroll
    for (int o = 0; o < C2; o++) {
        val[o] = g_agg2[v * C2 + o] * inv;
        mx = fmaxf(mx, val[o]);
    }
    float s = 0.f;
    #pragma unroll
    for (int o = 0; o < C2; o++) s += expf(val[o] - mx);
    float ls = mx + logf(s);
    #pragma unroll
    for (int o = 0; o < C2; o++) out[v * C2 + o] = val[o] - ls;
}

// ---------------- launch (inputs identified by element count) ----------------
extern "C" void kernel_launch(void* const* d_in, const int* in_sizes, int n_in,
                              void* d_out, int out_size) {
    const float* x  = nullptr;
    const int*   ei = nullptr;
    const float* W1 = nullptr;
    const float* b1 = nullptr;
    const float* W2 = nullptr;
    const float* b2 = nullptr;
    for (int k = 0; k < n_in; k++) {
        switch (in_sizes[k]) {
            case NN * INC:  x  = (const float*)d_in[k]; break;
            case 2 * EIN:   ei = (const int*)  d_in[k]; break;
            case C1 * INC:  W1 = (const float*)d_in[k]; break;
            case C1:        b1 = (const float*)d_in[k]; break;
            case C2 * C1:   W2 = (const float*)d_in[k]; break;
            case C2:        b2 = (const float*)d_in[k]; break;
            default: break;
        }
    }
    float* out = (float*)d_out;

    k_init   <<<(NN * C1 + 255) / 256, 256>>>();

    // layer 1
    k_gemm1  <<<NN, 512>>>(x, W1, b1);
    k_sort   <<<C1, 1024>>>(ei, 1);
    k_te     <<<C1 * BPC, 32 * WPB>>>(1);
    k_agg    <<<(ET * C1 + 255) / 256, 256>>>(ei, 1, C1);

    // layer 2
    k_gemm2  <<<(NN + 255) / 256, 256>>>(W2, b2);
    k_sort   <<<C2, 1024>>>(ei, 2);
    k_te     <<<C2 * BPC, 32 * WPB>>>(2);
    k_agg    <<<(ET * C2 + 255) / 256, 256>>>(ei, 2, C2);

    k_final  <<<(NN + 255) / 256, 256>>>(out);
}